// round 9
// baseline (speedup 1.0000x reference)
#include <cuda_runtime.h>
#include <cuda_bf16.h>
#include <math.h>
#include <stdint.h>

#define NB 8
#define SEQ 512
#define MAXSEQ 4096
#define DIM 512
#define INTER 1024
#define NLAYERS 4
#define P1 516
#define M1 (NB*P1)            // 4128 gemm1 rows (packed)
#define M1T 33                // ceil(4128/128)
#define CONST_W 3581.0f

// ---------------- scratch ----------------
__device__ float         g_x   [NB*SEQ*DIM];
__device__ __nv_bfloat16 g_a1h [(M1T*128)*DIM];
__device__ __nv_bfloat16 g_a1l [(M1T*128)*DIM];
__device__ float         g_h   [(M1T*128)*INTER];
__device__ __nv_bfloat16 g_a2h [NB*SEQ*INTER];
__device__ __nv_bfloat16 g_a2l [NB*SEQ*INTER];
__device__ __nv_bfloat16 g_w1h [NLAYERS*INTER*DIM];
__device__ __nv_bfloat16 g_w1l [NLAYERS*INTER*DIM];
__device__ __nv_bfloat16 g_w2h [NLAYERS*DIM*INTER];
__device__ __nv_bfloat16 g_w2l [NLAYERS*DIM*INTER];
__device__ float         g_sumsq[NB*INTER];
__device__ float         g_alpha[NB*INTER];
__device__ int           g_needfix[NB];

// ---------------- helpers ----------------
__device__ __forceinline__ uint32_t smem_u32(const void* p) {
    uint32_t a;
    asm("{ .reg .u64 t; cvta.to.shared.u64 t, %1; cvt.u32.u64 %0, t; }" : "=r"(a) : "l"(p));
    return a;
}

#define STAGE_BYTES 32768u      // A 16KB + B 16KB
#define NSTAGE 3

// ---------------- compute one 64-K stage: warp tile 64x64 (4 warps, 2x2) ----------------
__device__ __forceinline__ void compute_stage(uint32_t sbs,
                                              const uint32_t aoff[4], const uint32_t boff[4],
                                              float acc[4][8][4]) {
    #pragma unroll
    for (int ks = 0; ks < 4; ks++) {
        uint32_t kx = (uint32_t)ks * 32u;
        uint32_t a_frag[4][4];
        #pragma unroll
        for (int i = 0; i < 4; i++)
            asm volatile("ldmatrix.sync.aligned.m8n8.x4.shared.b16 {%0,%1,%2,%3}, [%4];"
                : "=r"(a_frag[i][0]), "=r"(a_frag[i][1]), "=r"(a_frag[i][2]), "=r"(a_frag[i][3])
                : "r"((sbs + aoff[i]) ^ kx));
        uint32_t b_frag[8][2];
        #pragma unroll
        for (int jj = 0; jj < 4; jj++) {
            uint32_t r0, r1, r2, r3;
            asm volatile("ldmatrix.sync.aligned.m8n8.x4.shared.b16 {%0,%1,%2,%3}, [%4];"
                : "=r"(r0), "=r"(r1), "=r"(r2), "=r"(r3) : "r"((sbs + boff[jj]) ^ kx));
            b_frag[jj*2+0][0] = r0; b_frag[jj*2+0][1] = r2;
            b_frag[jj*2+1][0] = r1; b_frag[jj*2+1][1] = r3;
        }
        #pragma unroll
        for (int i = 0; i < 4; i++)
            #pragma unroll
            for (int j = 0; j < 8; j++)
                asm volatile(
                    "mma.sync.aligned.m16n8k16.row.col.f32.bf16.bf16.f32 "
                    "{%0,%1,%2,%3}, {%4,%5,%6,%7}, {%8,%9}, {%0,%1,%2,%3};"
                    : "+f"(acc[i][j][0]), "+f"(acc[i][j][1]),
                      "+f"(acc[i][j][2]), "+f"(acc[i][j][3])
                    : "r"(a_frag[i][0]), "r"(a_frag[i][1]),
                      "r"(a_frag[i][2]), "r"(a_frag[i][3]),
                      "r"(b_frag[j][0]), "r"(b_frag[j][1]));
    }
}

// ---------------- mainloop over chunk range [c0, c1) ----------------
__device__ __forceinline__ void mma_mainloop(
    const __nv_bfloat16* a_hi, const __nv_bfloat16* a_lo,
    const __nv_bfloat16* b_hi, const __nv_bfloat16* b_lo,
    int K, int pc, int c0, int c1, int m0, int n0,
    uint32_t smem_base, int t, int warpM, int warpN, int lane,
    float acc[4][8][4]) {
    int lrow = t >> 3, lkg = t & 7;
    uint32_t so = (uint32_t)lrow * 128u + (((uint32_t)lkg * 16u) ^ (((uint32_t)lrow & 7u) * 16u));
    size_t srcoff = (size_t)lrow * K + lkg * 8;
    size_t rbytes = (size_t)16 * K * 2;

    const __nv_bfloat16* A0 = a_hi + (size_t)m0 * K + srcoff;
    const __nv_bfloat16* A1 = a_lo + (size_t)m0 * K + srcoff;
    const __nv_bfloat16* B0 = b_hi + (size_t)n0 * K + srcoff;
    const __nv_bfloat16* B2 = b_lo + (size_t)n0 * K + srcoff;

    int ph = c0 / pc;
    int kk = c0 - ph * pc;
    const __nv_bfloat16* pA = ((ph == 1) ? A1 : A0) + (size_t)kk * 64;
    const __nv_bfloat16* pB = B0 + (size_t)kk * 64;

    int la = lane & 15, lh = lane >> 4;
    uint32_t aoff[4], boff[4];
    #pragma unroll
    for (int i = 0; i < 4; i++) {
        uint32_t row = (uint32_t)(warpM * 64 + i * 16 + la);
        aoff[i] = row * 128u + (((uint32_t)lh * 16u) ^ ((row & 7u) * 16u));
    }
    #pragma unroll
    for (int jj = 0; jj < 4; jj++) {
        uint32_t row = (uint32_t)(warpN * 64 + jj * 16 + la);
        boff[jj] = 16384u + row * 128u + (((uint32_t)lh * 16u) ^ ((row & 7u) * 16u));
    }

#define ISSUE(slot) do { \
    uint32_t dst = smem_base + (uint32_t)(slot) * STAGE_BYTES; \
    const char* sa = (const char*)pA; const char* sb = (const char*)pB; \
    _Pragma("unroll") \
    for (int ii = 0; ii < 8; ii++) { \
        asm volatile("cp.async.cg.shared.global [%0], [%1], 16;" \
                     :: "r"(dst + so + (uint32_t)ii * 2048u), "l"(sa)); \
        asm volatile("cp.async.cg.shared.global [%0], [%1], 16;" \
                     :: "r"(dst + 16384u + so + (uint32_t)ii * 2048u), "l"(sb)); \
        sa += rbytes; sb += rbytes; } } while(0)

#define ADV() do { pA += 64; pB += 64; \
    if (++kk == pc) { kk = 0; ph++; \
        if (ph == 1) { pA = A1; pB = B0; } \
        else if (ph == 2) { pA = A0; pB = B2; } } } while(0)

    ISSUE(0); asm volatile("cp.async.commit_group;" ::: "memory"); ADV();
    ISSUE(1); asm volatile("cp.async.commit_group;" ::: "memory"); ADV();
    int stage = 0, pf_slot = 2;
    for (int kc = c0; kc < c1; kc++) {
        asm volatile("cp.async.wait_group 1;" ::: "memory");
        __syncthreads();
        if (kc + 2 < c1) {
            ISSUE(pf_slot); ADV();
            pf_slot = (pf_slot + 1 == NSTAGE) ? 0 : pf_slot + 1;
        }
        asm volatile("cp.async.commit_group;" ::: "memory");
        compute_stage(smem_base + (uint32_t)stage * STAGE_BYTES, aoff, boff, acc);
        stage = (stage + 1 == NSTAGE) ? 0 : stage + 1;
    }
#undef ISSUE
#undef ADV
}

__device__ __forceinline__ float gelu_exact(float v) {
    return 0.5f * v * (1.0f + erff(v * 0.7071067811865476f));
}

// ---------------- GEMM1: h = gelu(A1 @ W1t^T + b); writes h fp32 + bf16 split; GRN sumsq ----------------
__global__ void __launch_bounds__(128, 2) gemm1_mma(int l, const float* __restrict__ bias) {
    extern __shared__ char smem[];
    uint32_t sbase = smem_u32(smem);
    int t = threadIdx.x, lane = t & 31, wid = t >> 5;
    int warpM = wid & 1, warpN = wid >> 1;           // 2x2 warps, 64x64 tiles
    int n0 = blockIdx.x * 128, m0 = blockIdx.y * 128;
    float acc[4][8][4] = {};
    mma_mainloop(g_a1h, g_a1l,
                 g_w1h + (size_t)l * INTER * DIM, g_w1l + (size_t)l * INTER * DIM,
                 DIM, 8, 0, 24, m0, n0, sbase, t, warpM, warpN, lane, acc);
    int b_lo = m0 / P1;
    int boundary = (b_lo + 1) * P1;
    float cs[2][8][2] = {};
    #pragma unroll
    for (int i = 0; i < 4; i++) {
        #pragma unroll
        for (int half = 0; half < 2; half++) {
            int r = m0 + warpM * 64 + i * 16 + (lane >> 2) + 8 * half;
            int bs = (r >= boundary) ? 1 : 0;
            int p = r - (bs ? boundary : b_lo * P1);
            int b = b_lo + bs;
            float wgt = (r >= M1) ? 0.0f :
                        ((p < 515) ? 1.0f : ((p == 515) ? CONST_W : 0.0f));
            bool wr_a2 = (r < M1) && (p < 512);
            size_t row2 = (size_t)(b * SEQ + p) * INTER;
            #pragma unroll
            for (int j = 0; j < 8; j++) {
                int n = n0 + warpN * 64 + j * 8 + (lane & 3) * 2;
                float g0 = gelu_exact(acc[i][j][half*2+0] + bias[n]);
                float g1 = gelu_exact(acc[i][j][half*2+1] + bias[n+1]);
                cs[bs][j][0] += wgt * g0 * g0;
                cs[bs][j][1] += wgt * g1 * g1;
                if (r < M1)
                    *(float2*)&g_h[(size_t)r * INTER + n] = make_float2(g0, g1);
                if (wr_a2) {
                    // GRN fast path: alpha==1, grn_b==0 -> A2 = h (fixup_kernel repairs otherwise)
                    __nv_bfloat16 h0 = __float2bfloat16_rn(g0);
                    __nv_bfloat16 h1 = __float2bfloat16_rn(g1);
                    *(__nv_bfloat162*)&g_a2h[row2 + n] = __nv_bfloat162(h0, h1);
                    *(__nv_bfloat162*)&g_a2l[row2 + n] =
                        __nv_bfloat162(__float2bfloat16_rn(g0 - __bfloat162float(h0)),
                                       __float2bfloat16_rn(g1 - __bfloat162float(h1)));
                }
            }
        }
    }
    #pragma unroll
    for (int bs = 0; bs < 2; bs++)
        #pragma unroll
        for (int j = 0; j < 8; j++)
            #pragma unroll
            for (int s = 0; s < 2; s++) {
                float v = cs[bs][j][s];
                v += __shfl_xor_sync(0xffffffffu, v, 4);
                v += __shfl_xor_sync(0xffffffffu, v, 8);
                v += __shfl_xor_sync(0xffffffffu, v, 16);
                cs[bs][j][s] = v;
            }
    if (lane < 4) {
        #pragma unroll
        for (int j = 0; j < 8; j++) {
            int n = n0 + warpN * 64 + j * 8 + lane * 2;
            atomicAdd(&g_sumsq[b_lo * INTER + n],     cs[0][j][0]);
            atomicAdd(&g_sumsq[b_lo * INTER + n + 1], cs[0][j][1]);
            if (b_lo + 1 < NB) {
                atomicAdd(&g_sumsq[(b_lo + 1) * INTER + n],     cs[1][j][0]);
                atomicAdd(&g_sumsq[(b_lo + 1) * INTER + n + 1], cs[1][j][1]);
            }
        }
    }
}

// ---------------- GEMM2: x += A2 @ W2t^T + b  (K-split 2, atomic epilogue) ----------------
__global__ void __launch_bounds__(128, 2) gemm2_mma(int l, const float* __restrict__ bias) {
    extern __shared__ char smem[];
    uint32_t sbase = smem_u32(smem);
    int t = threadIdx.x, lane = t & 31, wid = t >> 5;
    int warpM = wid & 1, warpN = wid >> 1;
    int n0 = blockIdx.x * 128, m0 = blockIdx.y * 128;
    int split = blockIdx.z;
    float acc[4][8][4] = {};
    mma_mainloop(g_a2h, g_a2l,
                 g_w2h + (size_t)l * DIM * INTER, g_w2l + (size_t)l * DIM * INTER,
                 INTER, 16, split * 24, split * 24 + 24, m0, n0,
                 sbase, t, warpM, warpN, lane, acc);
    #pragma unroll
    for (int i = 0; i < 4; i++) {
        int rowbase = m0 + warpM * 64 + i * 16 + (lane >> 2);
        #pragma unroll
        for (int half = 0; half < 2; half++) {
            int m = rowbase + 8 * half;
            #pragma unroll
            for (int j = 0; j < 8; j++) {
                int n = n0 + warpN * 64 + j * 8 + (lane & 3) * 2;
                size_t xo = (size_t)m * DIM + n;
                float add0 = acc[i][j][half*2+0];
                float add1 = acc[i][j][half*2+1];
                if (split == 0) { add0 += bias[n]; add1 += bias[n+1]; }
                atomicAdd(&g_x[xo],     add0);
                atomicAdd(&g_x[xo + 1], add1);
            }
        }
    }
}

// ---------------- embed + abs pos enc (paired sincos) ----------------
__global__ void embed_kernel(const int* __restrict__ text, const float* __restrict__ emb) {
    int bp = blockIdx.x;
    int p = bp & 511, b = bp >> 9;
    int tok = text[b * SEQ + p] + 1;
    const float* erow = emb + (size_t)tok * DIM;
    float* orow = g_x + (size_t)bp * DIM;
    int i = threadIdx.x;
    float f   = expf(-9.210340371976184f * (float)i / 256.0f);
    float ang = (float)p * f;
    float sv, cv;
    sincosf(ang, &sv, &cv);
    orow[i]       = erow[i]       + cv;
    orow[i + 256] = erow[i + 256] + sv;
}

// ---------------- dwconv(k=7) + LayerNorm -> bf16 hi/lo (packed rows) ----------------
__global__ void convln_kernel(const float* __restrict__ dw_w, const float* __restrict__ dw_b,
                              const float* __restrict__ ln_g, const float* __restrict__ ln_b) {
    int bp = blockIdx.x;
    int b = bp / P1;
    int p = bp - b * P1;
    int t = threadIdx.x;
    float y[4];
    #pragma unroll
    for (int j = 0; j < 4; j++) {
        int c = t + j * 128;
        float acc = dw_b[c];
        #pragma unroll
        for (int k = 0; k < 7; k++) {
            int pp = p - 3 + k;
            if (pp >= 0 && pp < SEQ)
                acc += dw_w[k * DIM + c] * g_x[(size_t)(b * SEQ + pp) * DIM + c];
        }
        y[j] = acc;
    }
    float s = y[0]+y[1]+y[2]+y[3];
    float s2 = y[0]*y[0]+y[1]*y[1]+y[2]*y[2]+y[3]*y[3];
    #pragma unroll
    for (int off = 16; off; off >>= 1) {
        s  += __shfl_xor_sync(0xffffffffu, s,  off);
        s2 += __shfl_xor_sync(0xffffffffu, s2, off);
    }
    __shared__ float sh[8];
    int w = t >> 5;
    if ((t & 31) == 0) { sh[w] = s; sh[4 + w] = s2; }
    __syncthreads();
    float S  = sh[0]+sh[1]+sh[2]+sh[3];
    float S2 = sh[4]+sh[5]+sh[6]+sh[7];
    float mean = S * (1.0f/512.0f);
    float var  = S2 * (1.0f/512.0f) - mean * mean;
    float inv  = rsqrtf(var + 1e-6f);
    size_t base = (size_t)bp * DIM;
    #pragma unroll
    for (int j = 0; j < 4; j++) {
        int c = t + j * 128;
        float v = (y[j] - mean) * inv * ln_g[c] + ln_b[c];
        __nv_bfloat16 hi = __float2bfloat16_rn(v);
        g_a1h[base + c] = hi;
        g_a1l[base + c] = __float2bfloat16_rn(v - __bfloat162float(hi));
    }
}

// ---------------- GRN finalize: alpha + per-batch needfix flag; resets sumsq ----------------
__global__ void alpha_kernel(const float* __restrict__ grn_g, const float* __restrict__ grn_b) {
    int b = blockIdx.x;
    int i = threadIdx.x;
    float gx = sqrtf(g_sumsq[b * INTER + i]);
    g_sumsq[b * INTER + i] = 0.0f;
    float r = gx;
    #pragma unroll
    for (int off = 16; off; off >>= 1) r += __shfl_xor_sync(0xffffffffu, r, off);
    __shared__ float sh[32];
    __shared__ float meansh;
    if ((i & 31) == 0) sh[i >> 5] = r;
    __syncthreads();
    if (i < 32) {
        float v = sh[i];
        #pragma unroll
        for (int off = 16; off; off >>= 1) v += __shfl_xor_sync(0xffffffffu, v, off);
        if (i == 0) meansh = v * (1.0f/1024.0f);
    }
    __syncthreads();
    float nx = gx / (meansh + 1e-6f);
    float alpha = grn_g[i] * nx + 1.0f;
    g_alpha[b * INTER + i] = alpha;
    int bad = (alpha != 1.0f) || (grn_b[i] != 0.0f);
    int any = __syncthreads_or(bad);
    if (i == 0) g_needfix[b] = any;
}

// ---------------- fixup: only if GRN non-trivial — rewrite A2 split from h ----------------
__global__ void fixup_kernel(const float* __restrict__ grn_b) {
    int row = blockIdx.x;             // b*512 + p
    int b = row >> 9, p = row & 511;
    if (!g_needfix[b]) return;
    const float* h  = g_h + (size_t)(b * P1 + p) * INTER;
    const float* al = g_alpha + b * INTER;
    __nv_bfloat16* oh = g_a2h + (size_t)row * INTER;
    __nv_bfloat16* ol = g_a2l + (size_t)row * INTER;
    int i = threadIdx.x * 4;
    float4 hv = *(const float4*)&h[i];
    float4 av = *(const float4*)&al[i];
    float4 gb = *(const float4*)&grn_b[i];
    float v0 = av.x * hv.x + gb.x;
    float v1 = av.y * hv.y + gb.y;
    float v2 = av.z * hv.z + gb.z;
    float v3 = av.w * hv.w + gb.w;
    __nv_bfloat16 h0 = __float2bfloat16_rn(v0), h1 = __float2bfloat16_rn(v1);
    __nv_bfloat16 h2 = __float2bfloat16_rn(v2), h3 = __float2bfloat16_rn(v3);
    *(__nv_bfloat162*)&oh[i]     = __nv_bfloat162(h0, h1);
    *(__nv_bfloat162*)&oh[i + 2] = __nv_bfloat162(h2, h3);
    *(__nv_bfloat162*)&ol[i]     = __nv_bfloat162(__float2bfloat16_rn(v0 - __bfloat162float(h0)),
                                                  __float2bfloat16_rn(v1 - __bfloat162float(h1)));
    *(__nv_bfloat162*)&ol[i + 2] = __nv_bfloat162(__float2bfloat16_rn(v2 - __bfloat162float(h2)),
                                                  __float2bfloat16_rn(v3 - __bfloat162float(h3)));
}

// ---------------- weight transpose + hi/lo split ----------------
__global__ void prep_w(const float* __restrict__ pw1_w, const float* __restrict__ pw2_w) {
    int which = blockIdx.z & 1;
    int l = blockIdx.z >> 1;
    const float* src; __nv_bfloat16 *dh, *dl;
    int R, C;
    if (which == 0) { src = pw1_w + (size_t)l * DIM * INTER; R = DIM;  C = INTER;
                      dh = g_w1h + (size_t)l * INTER * DIM; dl = g_w1l + (size_t)l * INTER * DIM; }
    else            { src = pw2_w + (size_t)l * INTER * DIM; R = INTER; C = DIM;
                      dh = g_w2h + (size_t)l * DIM * INTER; dl = g_w2l + (size_t)l * DIM * INTER; }
    int cx = blockIdx.x * 32, ry = blockIdx.y * 32;
    if (cx >= C || ry >= R) return;
    __shared__ float tl[32][33];
    int tx = threadIdx.x, ty = threadIdx.y;
    #pragma unroll
    for (int i = 0; i < 4; i++)
        tl[ty * 4 + i][tx] = src[(size_t)(ry + ty * 4 + i) * C + cx + tx];
    __syncthreads();
    #pragma unroll
    for (int i = 0; i < 4; i++) {
        float w = tl[tx][ty * 4 + i];
        __nv_bfloat16 hi = __float2bfloat16_rn(w);
        size_t o = (size_t)(cx + ty * 4 + i) * R + ry + tx;
        dh[o] = hi;
        dl[o] = __float2bfloat16_rn(w - __bfloat162float(hi));
    }
}

// ---------------- upsample ----------------
__global__ void upsample_kernel(const int* __restrict__ seq_len, float* __restrict__ out) {
    int bp = blockIdx.x;
    int b = bp >> 12, p = bp & 4095;
    int al = seq_len[b];
    float4* orow = (float4*)(out + (size_t)bp * DIM);
    if (p >= al) {
        for (int c = threadIdx.x; c < DIM / 4; c += blockDim.x)
            orow[c] = make_float4(0.f, 0.f, 0.f, 0.f);
        return;
    }
    int base  = al >> 9;
    int rem   = al & 511;
    int split = (512 - rem) * base;
    int j = (p < split) ? (p / base) : ((512 - rem) + (p - split) / (base + 1));
    if (j > 511) j = 511;
    const float4* xrow = (const float4*)(g_x + (size_t)(b * SEQ + j) * DIM);
    for (int c = threadIdx.x; c < DIM / 4; c += blockDim.x) orow[c] = xrow[c];
}

// ---------------- launch ----------------
extern "C" void kernel_launch(void* const* d_in, const int* in_sizes, int n_in,
                              void* d_out, int out_size) {
    const int*   text    = (const int*)  d_in[0];
    const int*   seq_len = (const int*)  d_in[1];
    const float* emb     = (const float*)d_in[2];
    const float* dw_w    = (const float*)d_in[3];
    const float* dw_b    = (const float*)d_in[4];
    const float* ln_g    = (const float*)d_in[5];
    const float* ln_b    = (const float*)d_in[6];
    const float* pw1_w   = (const float*)d_in[7];
    const float* pw1_b   = (const float*)d_in[8];
    const float* grn_g   = (const float*)d_in[9];
    const float* grn_b   = (const float*)d_in[10];
    const float* pw2_w   = (const float*)d_in[11];
    const float* pw2_b   = (const float*)d_in[12];
    float* out = (float*)d_out;

    static const int SMEM_BYTES = NSTAGE * (int)STAGE_BYTES;  // 96 KB
    cudaFuncSetAttribute(gemm1_mma, cudaFuncAttributeMaxDynamicSharedMemorySize, SMEM_BYTES);
    cudaFuncSetAttribute(gemm2_mma, cudaFuncAttributeMaxDynamicSharedMemorySize, SMEM_BYTES);

    prep_w<<<dim3(32, 32, 2 * NLAYERS), dim3(32, 8)>>>(pw1_w, pw2_w);
    embed_kernel<<<NB * SEQ, 256>>>(text, emb);
    for (int l = 0; l < NLAYERS; l++) {
        convln_kernel<<<NB * P1, 128>>>(dw_w + l * 7 * DIM, dw_b + l * DIM,
                                        ln_g + l * DIM, ln_b + l * DIM);
        gemm1_mma<<<dim3(INTER / 128, M1T), 128, SMEM_BYTES>>>(l, pw1_b + l * INTER);
        alpha_kernel<<<NB, 1024>>>(grn_g + l * INTER, grn_b + l * INTER);
        fixup_kernel<<<NB * SEQ, 256>>>(grn_b + l * INTER);
        gemm2_mma<<<dim3(DIM / 128, NB * SEQ / 128, 2), 128, SMEM_BYTES>>>(l, pw2_b + l * DIM);
    }
    upsample_kernel<<<NB * MAXSEQ, 128>>>(seq_len, out);
}

// round 10
// speedup vs baseline: 1.2666x; 1.2666x over previous
#include <cuda_runtime.h>
#include <cuda_fp16.h>
#include <math.h>
#include <stdint.h>

#define NB 8
#define SEQ 512
#define MAXSEQ 4096
#define DIM 512
#define INTER 1024
#define NLAYERS 4
#define P1 516
#define M1 (NB*P1)            // 4128 gemm1 rows (packed)
#define M1T 33                // ceil(4128/128)
#define CONST_W 3581.0f

// ---------------- scratch ----------------
__device__ float  g_x   [NB*SEQ*DIM];
__device__ __half g_a1h [(M1T*128)*DIM];      // activations hi (rows >= 4128 stay zero)
__device__ __half g_a1l [(M1T*128)*DIM];      // activations lo
__device__ __half g_a2h [NB*SEQ*INTER];
__device__ __half g_a2l [NB*SEQ*INTER];
__device__ __half g_w1  [NLAYERS*INTER*DIM];  // pw1_w transposed [N][K], fp16
__device__ __half g_w2  [NLAYERS*DIM*INTER];  // pw2_w transposed [N][K], fp16
__device__ float  g_sumsq[NB*INTER];
__device__ float  g_alpha[NB*INTER];
__device__ int    g_needfix[NB];

// ---------------- helpers ----------------
__device__ __forceinline__ uint32_t smem_u32(const void* p) {
    uint32_t a;
    asm("{ .reg .u64 t; cvta.to.shared.u64 t, %1; cvt.u32.u64 %0, t; }" : "=r"(a) : "l"(p));
    return a;
}

#define STAGE_BYTES 32768u      // A 16KB + B 16KB
#define NSTAGE 3

// ---------------- compute one 64-K stage: warp tile 64x64 (4 warps, 2x2) ----------------
__device__ __forceinline__ void compute_stage(uint32_t sbs,
                                              const uint32_t aoff[4], const uint32_t boff[4],
                                              float acc[4][8][4]) {
    #pragma unroll
    for (int ks = 0; ks < 4; ks++) {
        uint32_t kx = (uint32_t)ks * 32u;
        uint32_t a_frag[4][4];
        #pragma unroll
        for (int i = 0; i < 4; i++)
            asm volatile("ldmatrix.sync.aligned.m8n8.x4.shared.b16 {%0,%1,%2,%3}, [%4];"
                : "=r"(a_frag[i][0]), "=r"(a_frag[i][1]), "=r"(a_frag[i][2]), "=r"(a_frag[i][3])
                : "r"((sbs + aoff[i]) ^ kx));
        uint32_t b_frag[8][2];
        #pragma unroll
        for (int jj = 0; jj < 4; jj++) {
            uint32_t r0, r1, r2, r3;
            asm volatile("ldmatrix.sync.aligned.m8n8.x4.shared.b16 {%0,%1,%2,%3}, [%4];"
                : "=r"(r0), "=r"(r1), "=r"(r2), "=r"(r3) : "r"((sbs + boff[jj]) ^ kx));
            b_frag[jj*2+0][0] = r0; b_frag[jj*2+0][1] = r2;
            b_frag[jj*2+1][0] = r1; b_frag[jj*2+1][1] = r3;
        }
        #pragma unroll
        for (int i = 0; i < 4; i++)
            #pragma unroll
            for (int j = 0; j < 8; j++)
                asm volatile(
                    "mma.sync.aligned.m16n8k16.row.col.f32.f16.f16.f32 "
                    "{%0,%1,%2,%3}, {%4,%5,%6,%7}, {%8,%9}, {%0,%1,%2,%3};"
                    : "+f"(acc[i][j][0]), "+f"(acc[i][j][1]),
                      "+f"(acc[i][j][2]), "+f"(acc[i][j][3])
                    : "r"(a_frag[i][0]), "r"(a_frag[i][1]),
                      "r"(a_frag[i][2]), "r"(a_frag[i][3]),
                      "r"(b_frag[j][0]), "r"(b_frag[j][1]));
    }
}

// ---------------- mainloop over chunk range [c0, c1): 2 phases (A_hi, A_lo) x B ----------------
__device__ __forceinline__ void mma_mainloop(
    const __half* a_hi, const __half* a_lo, const __half* b_w,
    int K, int pc, int c0, int c1, int m0, int n0,
    uint32_t smem_base, int t, int warpM, int warpN, int lane,
    float acc[4][8][4]) {
    int lrow = t >> 3, lkg = t & 7;
    uint32_t so = (uint32_t)lrow * 128u + (((uint32_t)lkg * 16u) ^ (((uint32_t)lrow & 7u) * 16u));
    size_t srcoff = (size_t)lrow * K + lkg * 8;
    size_t rbytes = (size_t)16 * K * 2;

    const __half* A0 = a_hi + (size_t)m0 * K + srcoff;
    const __half* A1 = a_lo + (size_t)m0 * K + srcoff;
    const __half* B0 = b_w  + (size_t)n0 * K + srcoff;

    int ph = c0 / pc;
    int kk = c0 - ph * pc;
    const __half* pA = ((ph == 1) ? A1 : A0) + (size_t)kk * 64;
    const __half* pB = B0 + (size_t)kk * 64;

    int la = lane & 15, lh = lane >> 4;
    uint32_t aoff[4], boff[4];
    #pragma unroll
    for (int i = 0; i < 4; i++) {
        uint32_t row = (uint32_t)(warpM * 64 + i * 16 + la);
        aoff[i] = row * 128u + (((uint32_t)lh * 16u) ^ ((row & 7u) * 16u));
    }
    #pragma unroll
    for (int jj = 0; jj < 4; jj++) {
        uint32_t row = (uint32_t)(warpN * 64 + jj * 16 + la);
        boff[jj] = 16384u + row * 128u + (((uint32_t)lh * 16u) ^ ((row & 7u) * 16u));
    }

#define ISSUE(slot) do { \
    uint32_t dst = smem_base + (uint32_t)(slot) * STAGE_BYTES; \
    const char* sa = (const char*)pA; const char* sb = (const char*)pB; \
    _Pragma("unroll") \
    for (int ii = 0; ii < 8; ii++) { \
        asm volatile("cp.async.cg.shared.global [%0], [%1], 16;" \
                     :: "r"(dst + so + (uint32_t)ii * 2048u), "l"(sa)); \
        asm volatile("cp.async.cg.shared.global [%0], [%1], 16;" \
                     :: "r"(dst + 16384u + so + (uint32_t)ii * 2048u), "l"(sb)); \
        sa += rbytes; sb += rbytes; } } while(0)

#define ADV() do { pA += 64; pB += 64; \
    if (++kk == pc) { kk = 0; ph++; pA = A1; pB = B0; } } while(0)

    ISSUE(0); asm volatile("cp.async.commit_group;" ::: "memory"); ADV();
    ISSUE(1); asm volatile("cp.async.commit_group;" ::: "memory"); ADV();
    int stage = 0, pf_slot = 2;
    for (int kc = c0; kc < c1; kc++) {
        asm volatile("cp.async.wait_group 1;" ::: "memory");
        __syncthreads();
        if (kc + 2 < c1) {
            ISSUE(pf_slot); ADV();
            pf_slot = (pf_slot + 1 == NSTAGE) ? 0 : pf_slot + 1;
        }
        asm volatile("cp.async.commit_group;" ::: "memory");
        compute_stage(smem_base + (uint32_t)stage * STAGE_BYTES, aoff, boff, acc);
        stage = (stage + 1 == NSTAGE) ? 0 : stage + 1;
    }
#undef ISSUE
#undef ADV
}

__device__ __forceinline__ float gelu_exact(float v) {
    return 0.5f * v * (1.0f + erff(v * 0.7071067811865476f));
}

// ---------------- GEMM1: h = gelu(A1 @ W1t^T + b); writes fp16 split of h; GRN sumsq ----------------
__global__ void __launch_bounds__(128, 2) gemm1_mma(int l, const float* __restrict__ bias) {
    extern __shared__ char smem[];
    uint32_t sbase = smem_u32(smem);
    int t = threadIdx.x, lane = t & 31, wid = t >> 5;
    int warpM = wid & 1, warpN = wid >> 1;           // 2x2 warps, 64x64 tiles
    int n0 = blockIdx.x * 128, m0 = blockIdx.y * 128;
    float acc[4][8][4] = {};
    mma_mainloop(g_a1h, g_a1l, g_w1 + (size_t)l * INTER * DIM,
                 DIM, 8, 0, 16, m0, n0, sbase, t, warpM, warpN, lane, acc);
    int b_lo = m0 / P1;
    int boundary = (b_lo + 1) * P1;
    float cs[2][8][2] = {};
    #pragma unroll
    for (int i = 0; i < 4; i++) {
        #pragma unroll
        for (int half = 0; half < 2; half++) {
            int r = m0 + warpM * 64 + i * 16 + (lane >> 2) + 8 * half;
            int bs = (r >= boundary) ? 1 : 0;
            int p = r - (bs ? boundary : b_lo * P1);
            int b = b_lo + bs;
            float wgt = (r >= M1) ? 0.0f :
                        ((p < 515) ? 1.0f : ((p == 515) ? CONST_W : 0.0f));
            bool wr_a2 = (r < M1) && (p < 512);
            size_t row2 = (size_t)(b * SEQ + p) * INTER;
            #pragma unroll
            for (int j = 0; j < 8; j++) {
                int n = n0 + warpN * 64 + j * 8 + (lane & 3) * 2;
                float g0 = gelu_exact(acc[i][j][half*2+0] + bias[n]);
                float g1 = gelu_exact(acc[i][j][half*2+1] + bias[n+1]);
                cs[bs][j][0] += wgt * g0 * g0;
                cs[bs][j][1] += wgt * g1 * g1;
                if (wr_a2) {
                    // GRN fast path: alpha==1, grn_b==0 -> A2 = h (fixup_kernel repairs otherwise)
                    __half h0 = __float2half_rn(g0);
                    __half h1 = __float2half_rn(g1);
                    *(__half2*)&g_a2h[row2 + n] = __half2(h0, h1);
                    *(__half2*)&g_a2l[row2 + n] =
                        __half2(__float2half_rn(g0 - __half2float(h0)),
                                __float2half_rn(g1 - __half2float(h1)));
                }
            }
        }
    }
    #pragma unroll
    for (int bs = 0; bs < 2; bs++)
        #pragma unroll
        for (int j = 0; j < 8; j++)
            #pragma unroll
            for (int s = 0; s < 2; s++) {
                float v = cs[bs][j][s];
                v += __shfl_xor_sync(0xffffffffu, v, 4);
                v += __shfl_xor_sync(0xffffffffu, v, 8);
                v += __shfl_xor_sync(0xffffffffu, v, 16);
                cs[bs][j][s] = v;
            }
    if (lane < 4) {
        #pragma unroll
        for (int j = 0; j < 8; j++) {
            int n = n0 + warpN * 64 + j * 8 + lane * 2;
            atomicAdd(&g_sumsq[b_lo * INTER + n],     cs[0][j][0]);
            atomicAdd(&g_sumsq[b_lo * INTER + n + 1], cs[0][j][1]);
            if (b_lo + 1 < NB) {
                atomicAdd(&g_sumsq[(b_lo + 1) * INTER + n],     cs[1][j][0]);
                atomicAdd(&g_sumsq[(b_lo + 1) * INTER + n + 1], cs[1][j][1]);
            }
        }
    }
}

// ---------------- GEMM2: x += A2 @ W2t^T + b  (K-split 2 = phase split, atomic epilogue) ----------------
__global__ void __launch_bounds__(128, 2) gemm2_mma(int l, const float* __restrict__ bias) {
    extern __shared__ char smem[];
    uint32_t sbase = smem_u32(smem);
    int t = threadIdx.x, lane = t & 31, wid = t >> 5;
    int warpM = wid & 1, warpN = wid >> 1;
    int n0 = blockIdx.x * 128, m0 = blockIdx.y * 128;
    int split = blockIdx.z;
    float acc[4][8][4] = {};
    mma_mainloop(g_a2h, g_a2l, g_w2 + (size_t)l * DIM * INTER,
                 INTER, 16, split * 16, split * 16 + 16, m0, n0,
                 sbase, t, warpM, warpN, lane, acc);
    #pragma unroll
    for (int i = 0; i < 4; i++) {
        int rowbase = m0 + warpM * 64 + i * 16 + (lane >> 2);
        #pragma unroll
        for (int half = 0; half < 2; half++) {
            int m = rowbase + 8 * half;
            #pragma unroll
            for (int j = 0; j < 8; j++) {
                int n = n0 + warpN * 64 + j * 8 + (lane & 3) * 2;
                size_t xo = (size_t)m * DIM + n;
                float add0 = acc[i][j][half*2+0];
                float add1 = acc[i][j][half*2+1];
                if (split == 0) { add0 += bias[n]; add1 += bias[n+1]; }
                atomicAdd(&g_x[xo],     add0);
                atomicAdd(&g_x[xo + 1], add1);
            }
        }
    }
}

// ---------------- embed + abs pos enc (paired sincos) ----------------
__global__ void embed_kernel(const int* __restrict__ text, const float* __restrict__ emb) {
    int bp = blockIdx.x;
    int p = bp & 511, b = bp >> 9;
    int tok = text[b * SEQ + p] + 1;
    const float* erow = emb + (size_t)tok * DIM;
    float* orow = g_x + (size_t)bp * DIM;
    int i = threadIdx.x;
    float f   = expf(-9.210340371976184f * (float)i / 256.0f);
    float ang = (float)p * f;
    float sv, cv;
    sincosf(ang, &sv, &cv);
    orow[i]       = erow[i]       + cv;
    orow[i + 256] = erow[i + 256] + sv;
}

// ---------------- dwconv(k=7) + LayerNorm -> fp16 hi/lo (packed rows) ----------------
__global__ void convln_kernel(const float* __restrict__ dw_w, const float* __restrict__ dw_b,
                              const float* __restrict__ ln_g, const float* __restrict__ ln_b) {
    int bp = blockIdx.x;
    int b = bp / P1;
    int p = bp - b * P1;
    int t = threadIdx.x;
    float y[4];
    #pragma unroll
    for (int j = 0; j < 4; j++) {
        int c = t + j * 128;
        float acc = dw_b[c];
        #pragma unroll
        for (int k = 0; k < 7; k++) {
            int pp = p - 3 + k;
            if (pp >= 0 && pp < SEQ)
                acc += dw_w[k * DIM + c] * g_x[(size_t)(b * SEQ + pp) * DIM + c];
        }
        y[j] = acc;
    }
    float s = y[0]+y[1]+y[2]+y[3];
    float s2 = y[0]*y[0]+y[1]*y[1]+y[2]*y[2]+y[3]*y[3];
    #pragma unroll
    for (int off = 16; off; off >>= 1) {
        s  += __shfl_xor_sync(0xffffffffu, s,  off);
        s2 += __shfl_xor_sync(0xffffffffu, s2, off);
    }
    __shared__ float sh[8];
    int w = t >> 5;
    if ((t & 31) == 0) { sh[w] = s; sh[4 + w] = s2; }
    __syncthreads();
    float S  = sh[0]+sh[1]+sh[2]+sh[3];
    float S2 = sh[4]+sh[5]+sh[6]+sh[7];
    float mean = S * (1.0f/512.0f);
    float var  = S2 * (1.0f/512.0f) - mean * mean;
    float inv  = rsqrtf(var + 1e-6f);
    size_t base = (size_t)bp * DIM;
    #pragma unroll
    for (int j = 0; j < 4; j++) {
        int c = t + j * 128;
        float v = (y[j] - mean) * inv * ln_g[c] + ln_b[c];
        __half hi = __float2half_rn(v);
        g_a1h[base + c] = hi;
        g_a1l[base + c] = __float2half_rn(v - __half2float(hi));
    }
}

// ---------------- GRN finalize: alpha + per-batch needfix flag; resets sumsq ----------------
__global__ void alpha_kernel(const float* __restrict__ grn_g, const float* __restrict__ grn_b) {
    int b = blockIdx.x;
    int i = threadIdx.x;
    float gx = sqrtf(g_sumsq[b * INTER + i]);
    g_sumsq[b * INTER + i] = 0.0f;
    float r = gx;
    #pragma unroll
    for (int off = 16; off; off >>= 1) r += __shfl_xor_sync(0xffffffffu, r, off);
    __shared__ float sh[32];
    __shared__ float meansh;
    if ((i & 31) == 0) sh[i >> 5] = r;
    __syncthreads();
    if (i < 32) {
        float v = sh[i];
        #pragma unroll
        for (int off = 16; off; off >>= 1) v += __shfl_xor_sync(0xffffffffu, v, off);
        if (i == 0) meansh = v * (1.0f/1024.0f);
    }
    __syncthreads();
    float nx = gx / (meansh + 1e-6f);
    float alpha = grn_g[i] * nx + 1.0f;
    g_alpha[b * INTER + i] = alpha;
    int bad = (alpha != 1.0f) || (grn_b[i] != 0.0f);
    int any = __syncthreads_or(bad);
    if (i == 0) g_needfix[b] = any;
}

// ---------------- fixup: only if GRN non-trivial — reconstruct h from split, rewrite A2 ----------------
__global__ void fixup_kernel(const float* __restrict__ grn_b) {
    int row = blockIdx.x;             // b*512 + p
    int b = row >> 9;
    if (!g_needfix[b]) return;
    const float* al = g_alpha + b * INTER;
    __half* oh = g_a2h + (size_t)row * INTER;
    __half* ol = g_a2l + (size_t)row * INTER;
    int i = threadIdx.x * 2;          // 512 threads x 2
    __half2 hh = *(__half2*)&oh[i];
    __half2 hl = *(__half2*)&ol[i];
    float h0 = __half2float(hh.x) + __half2float(hl.x);
    float h1 = __half2float(hh.y) + __half2float(hl.y);
    float v0 = al[i]     * h0 + grn_b[i];
    float v1 = al[i + 1] * h1 + grn_b[i + 1];
    __half n0 = __float2half_rn(v0), n1 = __float2half_rn(v1);
    *(__half2*)&oh[i] = __half2(n0, n1);
    *(__half2*)&ol[i] = __half2(__float2half_rn(v0 - __half2float(n0)),
                                __float2half_rn(v1 - __half2float(n1)));
}

// ---------------- weight transpose + fp16 ----------------
__global__ void prep_w(const float* __restrict__ pw1_w, const float* __restrict__ pw2_w) {
    int which = blockIdx.z & 1;
    int l = blockIdx.z >> 1;
    const float* src; __half* dh;
    int R, C;
    if (which == 0) { src = pw1_w + (size_t)l * DIM * INTER; R = DIM;  C = INTER;
                      dh = g_w1 + (size_t)l * INTER * DIM; }
    else            { src = pw2_w + (size_t)l * INTER * DIM; R = INTER; C = DIM;
                      dh = g_w2 + (size_t)l * DIM * INTER; }
    int cx = blockIdx.x * 32, ry = blockIdx.y * 32;
    if (cx >= C || ry >= R) return;
    __shared__ float tl[32][33];
    int tx = threadIdx.x, ty = threadIdx.y;
    #pragma unroll
    for (int i = 0; i < 4; i++)
        tl[ty * 4 + i][tx] = src[(size_t)(ry + ty * 4 + i) * C + cx + tx];
    __syncthreads();
    #pragma unroll
    for (int i = 0; i < 4; i++)
        dh[(size_t)(cx + ty * 4 + i) * R + ry + tx] = __float2half_rn(tl[tx][ty * 4 + i]);
}

// ---------------- upsample ----------------
__global__ void upsample_kernel(const int* __restrict__ seq_len, float* __restrict__ out) {
    int bp = blockIdx.x;
    int b = bp >> 12, p = bp & 4095;
    int al = seq_len[b];
    float4* orow = (float4*)(out + (size_t)bp * DIM);
    if (p >= al) {
        for (int c = threadIdx.x; c < DIM / 4; c += blockDim.x)
            orow[c] = make_float4(0.f, 0.f, 0.f, 0.f);
        return;
    }
    int base  = al >> 9;
    int rem   = al & 511;
    int split = (512 - rem) * base;
    int j = (p < split) ? (p / base) : ((512 - rem) + (p - split) / (base + 1));
    if (j > 511) j = 511;
    const float4* xrow = (const float4*)(g_x + (size_t)(b * SEQ + j) * DIM);
    for (int c = threadIdx.x; c < DIM / 4; c += blockDim.x) orow[c] = xrow[c];
}

// ---------------- launch ----------------
extern "C" void kernel_launch(void* const* d_in, const int* in_sizes, int n_in,
                              void* d_out, int out_size) {
    const int*   text    = (const int*)  d_in[0];
    const int*   seq_len = (const int*)  d_in[1];
    const float* emb     = (const float*)d_in[2];
    const float* dw_w    = (const float*)d_in[3];
    const float* dw_b    = (const float*)d_in[4];
    const float* ln_g    = (const float*)d_in[5];
    const float* ln_b    = (const float*)d_in[6];
    const float* pw1_w   = (const float*)d_in[7];
    const float* pw1_b   = (const float*)d_in[8];
    const float* grn_g   = (const float*)d_in[9];
    const float* grn_b   = (const float*)d_in[10];
    const float* pw2_w   = (const float*)d_in[11];
    const float* pw2_b   = (const float*)d_in[12];
    float* out = (float*)d_out;

    static const int SMEM_BYTES = NSTAGE * (int)STAGE_BYTES;  // 96 KB
    cudaFuncSetAttribute(gemm1_mma, cudaFuncAttributeMaxDynamicSharedMemorySize, SMEM_BYTES);
    cudaFuncSetAttribute(gemm2_mma, cudaFuncAttributeMaxDynamicSharedMemorySize, SMEM_BYTES);

    prep_w<<<dim3(32, 32, 2 * NLAYERS), dim3(32, 8)>>>(pw1_w, pw2_w);
    embed_kernel<<<NB * SEQ, 256>>>(text, emb);
    for (int l = 0; l < NLAYERS; l++) {
        convln_kernel<<<NB * P1, 128>>>(dw_w + l * 7 * DIM, dw_b + l * DIM,
                                        ln_g + l * DIM, ln_b + l * DIM);
        gemm1_mma<<<dim3(INTER / 128, M1T), 128, SMEM_BYTES>>>(l, pw1_b + l * INTER);
        alpha_kernel<<<NB, 1024>>>(grn_g + l * INTER, grn_b + l * INTER);
        fixup_kernel<<<NB * SEQ, 512>>>(grn_b + l * INTER);
        gemm2_mma<<<dim3(DIM / 128, NB * SEQ / 128, 2), 128, SMEM_BYTES>>>(l, pw2_b + l * DIM);
    }
    upsample_kernel<<<NB * MAXSEQ, 128>>>(seq_len, out);
}

// round 11
// speedup vs baseline: 1.7756x; 1.4018x over previous
#include <cuda_runtime.h>
#include <cuda_fp16.h>
#include <math.h>
#include <stdint.h>

#define NB 8
#define SEQ 512
#define MAXSEQ 4096
#define DIM 512
#define INTER 1024
#define NLAYERS 4
#define P1 516
#define M1 (NB*P1)            // 4128 gemm1 rows (packed)
#define M1T 33                // ceil(4128/128)
#define CONST_W 3581.0f

// ---------------- scratch ----------------
__device__ float  g_x   [NB*SEQ*DIM];
__device__ __half g_a1  [(M1T*128)*DIM];      // activations fp16 (rows >= 4128 stay zero)
__device__ __half g_a2  [NB*SEQ*INTER];
__device__ __half g_w1  [NLAYERS*INTER*DIM];  // pw1_w transposed [N][K], fp16
__device__ __half g_w2  [NLAYERS*DIM*INTER];  // pw2_w transposed [N][K], fp16
__device__ float  g_sumsq[NB*INTER];
__device__ float  g_alpha[NB*INTER];
__device__ int    g_needfix[NB];

// ---------------- helpers ----------------
__device__ __forceinline__ uint32_t smem_u32(const void* p) {
    uint32_t a;
    asm("{ .reg .u64 t; cvta.to.shared.u64 t, %1; cvt.u32.u64 %0, t; }" : "=r"(a) : "l"(p));
    return a;
}

#define STAGE_BYTES 32768u      // A 16KB + B 16KB
#define NSTAGE 3

// ---------------- compute one 64-K stage: warp tile 64x64 (4 warps, 2x2) ----------------
__device__ __forceinline__ void compute_stage(uint32_t sbs,
                                              const uint32_t aoff[4], const uint32_t boff[4],
                                              float acc[4][8][4]) {
    #pragma unroll
    for (int ks = 0; ks < 4; ks++) {
        uint32_t kx = (uint32_t)ks * 32u;
        uint32_t a_frag[4][4];
        #pragma unroll
        for (int i = 0; i < 4; i++)
            asm volatile("ldmatrix.sync.aligned.m8n8.x4.shared.b16 {%0,%1,%2,%3}, [%4];"
                : "=r"(a_frag[i][0]), "=r"(a_frag[i][1]), "=r"(a_frag[i][2]), "=r"(a_frag[i][3])
                : "r"((sbs + aoff[i]) ^ kx));
        uint32_t b_frag[8][2];
        #pragma unroll
        for (int jj = 0; jj < 4; jj++) {
            uint32_t r0, r1, r2, r3;
            asm volatile("ldmatrix.sync.aligned.m8n8.x4.shared.b16 {%0,%1,%2,%3}, [%4];"
                : "=r"(r0), "=r"(r1), "=r"(r2), "=r"(r3) : "r"((sbs + boff[jj]) ^ kx));
            b_frag[jj*2+0][0] = r0; b_frag[jj*2+0][1] = r2;
            b_frag[jj*2+1][0] = r1; b_frag[jj*2+1][1] = r3;
        }
        #pragma unroll
        for (int i = 0; i < 4; i++)
            #pragma unroll
            for (int j = 0; j < 8; j++)
                asm volatile(
                    "mma.sync.aligned.m16n8k16.row.col.f32.f16.f16.f32 "
                    "{%0,%1,%2,%3}, {%4,%5,%6,%7}, {%8,%9}, {%0,%1,%2,%3};"
                    : "+f"(acc[i][j][0]), "+f"(acc[i][j][1]),
                      "+f"(acc[i][j][2]), "+f"(acc[i][j][3])
                    : "r"(a_frag[i][0]), "r"(a_frag[i][1]),
                      "r"(a_frag[i][2]), "r"(a_frag[i][3]),
                      "r"(b_frag[j][0]), "r"(b_frag[j][1]));
    }
}

// ---------------- mainloop over chunk range [c0, c1): single fp16 phase ----------------
__device__ __forceinline__ void mma_mainloop(
    const __half* A, const __half* B, int K, int c0, int c1, int m0, int n0,
    uint32_t smem_base, int t, int warpM, int warpN, int lane,
    float acc[4][8][4]) {
    int lrow = t >> 3, lkg = t & 7;
    uint32_t so = (uint32_t)lrow * 128u + (((uint32_t)lkg * 16u) ^ (((uint32_t)lrow & 7u) * 16u));
    size_t srcoff = (size_t)lrow * K + lkg * 8;
    size_t rbytes = (size_t)16 * K * 2;

    const __half* pA = A + (size_t)m0 * K + srcoff + (size_t)c0 * 64;
    const __half* pB = B + (size_t)n0 * K + srcoff + (size_t)c0 * 64;

    int la = lane & 15, lh = lane >> 4;
    uint32_t aoff[4], boff[4];
    #pragma unroll
    for (int i = 0; i < 4; i++) {
        uint32_t row = (uint32_t)(warpM * 64 + i * 16 + la);
        aoff[i] = row * 128u + (((uint32_t)lh * 16u) ^ ((row & 7u) * 16u));
    }
    #pragma unroll
    for (int jj = 0; jj < 4; jj++) {
        uint32_t row = (uint32_t)(warpN * 64 + jj * 16 + la);
        boff[jj] = 16384u + row * 128u + (((uint32_t)lh * 16u) ^ ((row & 7u) * 16u));
    }

#define ISSUE(slot) do { \
    uint32_t dst = smem_base + (uint32_t)(slot) * STAGE_BYTES; \
    const char* sa = (const char*)pA; const char* sb = (const char*)pB; \
    _Pragma("unroll") \
    for (int ii = 0; ii < 8; ii++) { \
        asm volatile("cp.async.cg.shared.global [%0], [%1], 16;" \
                     :: "r"(dst + so + (uint32_t)ii * 2048u), "l"(sa)); \
        asm volatile("cp.async.cg.shared.global [%0], [%1], 16;" \
                     :: "r"(dst + 16384u + so + (uint32_t)ii * 2048u), "l"(sb)); \
        sa += rbytes; sb += rbytes; } \
    pA += 64; pB += 64; } while(0)

    ISSUE(0); asm volatile("cp.async.commit_group;" ::: "memory");
    ISSUE(1); asm volatile("cp.async.commit_group;" ::: "memory");
    int stage = 0, pf_slot = 2;
    for (int kc = c0; kc < c1; kc++) {
        asm volatile("cp.async.wait_group 1;" ::: "memory");
        __syncthreads();
        if (kc + 2 < c1) {
            ISSUE(pf_slot);
            pf_slot = (pf_slot + 1 == NSTAGE) ? 0 : pf_slot + 1;
        }
        asm volatile("cp.async.commit_group;" ::: "memory");
        compute_stage(smem_base + (uint32_t)stage * STAGE_BYTES, aoff, boff, acc);
        stage = (stage + 1 == NSTAGE) ? 0 : stage + 1;
    }
#undef ISSUE
}

__device__ __forceinline__ float gelu_exact(float v) {
    return 0.5f * v * (1.0f + erff(v * 0.7071067811865476f));
}

// ---------------- GEMM1: h = gelu(A1 @ W1t^T + b); writes fp16 h; GRN sumsq ----------------
__global__ void __launch_bounds__(128, 2) gemm1_mma(int l, const float* __restrict__ bias) {
    extern __shared__ char smem[];
    uint32_t sbase = smem_u32(smem);
    int t = threadIdx.x, lane = t & 31, wid = t >> 5;
    int warpM = wid & 1, warpN = wid >> 1;           // 2x2 warps, 64x64 tiles
    int n0 = blockIdx.x * 128, m0 = blockIdx.y * 128;
    float acc[4][8][4] = {};
    mma_mainloop(g_a1, g_w1 + (size_t)l * INTER * DIM,
                 DIM, 0, 8, m0, n0, sbase, t, warpM, warpN, lane, acc);
    int b_lo = m0 / P1;
    int boundary = (b_lo + 1) * P1;
    float cs[2][8][2] = {};
    #pragma unroll
    for (int i = 0; i < 4; i++) {
        #pragma unroll
        for (int half = 0; half < 2; half++) {
            int r = m0 + warpM * 64 + i * 16 + (lane >> 2) + 8 * half;
            int bs = (r >= boundary) ? 1 : 0;
            int p = r - (bs ? boundary : b_lo * P1);
            int b = b_lo + bs;
            float wgt = (r >= M1) ? 0.0f :
                        ((p < 515) ? 1.0f : ((p == 515) ? CONST_W : 0.0f));
            bool wr_a2 = (r < M1) && (p < 512);
            size_t row2 = (size_t)(b * SEQ + p) * INTER;
            #pragma unroll
            for (int j = 0; j < 8; j++) {
                int n = n0 + warpN * 64 + j * 8 + (lane & 3) * 2;
                float g0 = gelu_exact(acc[i][j][half*2+0] + bias[n]);
                float g1 = gelu_exact(acc[i][j][half*2+1] + bias[n+1]);
                cs[bs][j][0] += wgt * g0 * g0;
                cs[bs][j][1] += wgt * g1 * g1;
                if (wr_a2) {
                    // GRN fast path: alpha==1, grn_b==0 -> A2 = h (fixup_kernel repairs otherwise)
                    *(__half2*)&g_a2[row2 + n] =
                        __half2(__float2half_rn(g0), __float2half_rn(g1));
                }
            }
        }
    }
    #pragma unroll
    for (int bs = 0; bs < 2; bs++)
        #pragma unroll
        for (int j = 0; j < 8; j++)
            #pragma unroll
            for (int s = 0; s < 2; s++) {
                float v = cs[bs][j][s];
                v += __shfl_xor_sync(0xffffffffu, v, 4);
                v += __shfl_xor_sync(0xffffffffu, v, 8);
                v += __shfl_xor_sync(0xffffffffu, v, 16);
                cs[bs][j][s] = v;
            }
    if (lane < 4) {
        #pragma unroll
        for (int j = 0; j < 8; j++) {
            int n = n0 + warpN * 64 + j * 8 + lane * 2;
            atomicAdd(&g_sumsq[b_lo * INTER + n],     cs[0][j][0]);
            atomicAdd(&g_sumsq[b_lo * INTER + n + 1], cs[0][j][1]);
            if (b_lo + 1 < NB) {
                atomicAdd(&g_sumsq[(b_lo + 1) * INTER + n],     cs[1][j][0]);
                atomicAdd(&g_sumsq[(b_lo + 1) * INTER + n + 1], cs[1][j][1]);
            }
        }
    }
}

// ---------------- GEMM2: x += A2 @ W2t^T + b  (K-split 2, atomic epilogue) ----------------
__global__ void __launch_bounds__(128, 2) gemm2_mma(int l, const float* __restrict__ bias) {
    extern __shared__ char smem[];
    uint32_t sbase = smem_u32(smem);
    int t = threadIdx.x, lane = t & 31, wid = t >> 5;
    int warpM = wid & 1, warpN = wid >> 1;
    int n0 = blockIdx.x * 128, m0 = blockIdx.y * 128;
    int split = blockIdx.z;
    float acc[4][8][4] = {};
    mma_mainloop(g_a2, g_w2 + (size_t)l * DIM * INTER,
                 INTER, split * 8, split * 8 + 8, m0, n0,
                 sbase, t, warpM, warpN, lane, acc);
    #pragma unroll
    for (int i = 0; i < 4; i++) {
        int rowbase = m0 + warpM * 64 + i * 16 + (lane >> 2);
        #pragma unroll
        for (int half = 0; half < 2; half++) {
            int m = rowbase + 8 * half;
            #pragma unroll
            for (int j = 0; j < 8; j++) {
                int n = n0 + warpN * 64 + j * 8 + (lane & 3) * 2;
                size_t xo = (size_t)m * DIM + n;
                float add0 = acc[i][j][half*2+0];
                float add1 = acc[i][j][half*2+1];
                if (split == 0) { add0 += bias[n]; add1 += bias[n+1]; }
                atomicAdd(&g_x[xo],     add0);
                atomicAdd(&g_x[xo + 1], add1);
            }
        }
    }
}

// ---------------- embed + abs pos enc (paired sincos) ----------------
__global__ void embed_kernel(const int* __restrict__ text, const float* __restrict__ emb) {
    int bp = blockIdx.x;
    int p = bp & 511, b = bp >> 9;
    int tok = text[b * SEQ + p] + 1;
    const float* erow = emb + (size_t)tok * DIM;
    float* orow = g_x + (size_t)bp * DIM;
    int i = threadIdx.x;
    float f   = expf(-9.210340371976184f * (float)i / 256.0f);
    float ang = (float)p * f;
    float sv, cv;
    sincosf(ang, &sv, &cv);
    orow[i]       = erow[i]       + cv;
    orow[i + 256] = erow[i + 256] + sv;
}

// ---------------- dwconv(k=7) + LayerNorm -> fp16 (packed rows) ----------------
__global__ void convln_kernel(const float* __restrict__ dw_w, const float* __restrict__ dw_b,
                              const float* __restrict__ ln_g, const float* __restrict__ ln_b) {
    int bp = blockIdx.x;
    int b = bp / P1;
    int p = bp - b * P1;
    int t = threadIdx.x;
    float y[4];
    #pragma unroll
    for (int j = 0; j < 4; j++) {
        int c = t + j * 128;
        float acc = dw_b[c];
        #pragma unroll
        for (int k = 0; k < 7; k++) {
            int pp = p - 3 + k;
            if (pp >= 0 && pp < SEQ)
                acc += dw_w[k * DIM + c] * g_x[(size_t)(b * SEQ + pp) * DIM + c];
        }
        y[j] = acc;
    }
    float s = y[0]+y[1]+y[2]+y[3];
    float s2 = y[0]*y[0]+y[1]*y[1]+y[2]*y[2]+y[3]*y[3];
    #pragma unroll
    for (int off = 16; off; off >>= 1) {
        s  += __shfl_xor_sync(0xffffffffu, s,  off);
        s2 += __shfl_xor_sync(0xffffffffu, s2, off);
    }
    __shared__ float sh[8];
    int w = t >> 5;
    if ((t & 31) == 0) { sh[w] = s; sh[4 + w] = s2; }
    __syncthreads();
    float S  = sh[0]+sh[1]+sh[2]+sh[3];
    float S2 = sh[4]+sh[5]+sh[6]+sh[7];
    float mean = S * (1.0f/512.0f);
    float var  = S2 * (1.0f/512.0f) - mean * mean;
    float inv  = rsqrtf(var + 1e-6f);
    size_t base = (size_t)bp * DIM;
    #pragma unroll
    for (int j = 0; j < 4; j++) {
        int c = t + j * 128;
        float v = (y[j] - mean) * inv * ln_g[c] + ln_b[c];
        g_a1[base + c] = __float2half_rn(v);
    }
}

// ---------------- GRN finalize: alpha + per-batch needfix flag; resets sumsq ----------------
__global__ void alpha_kernel(const float* __restrict__ grn_g, const float* __restrict__ grn_b) {
    int b = blockIdx.x;
    int i = threadIdx.x;
    float gx = sqrtf(g_sumsq[b * INTER + i]);
    g_sumsq[b * INTER + i] = 0.0f;
    float r = gx;
    #pragma unroll
    for (int off = 16; off; off >>= 1) r += __shfl_xor_sync(0xffffffffu, r, off);
    __shared__ float sh[32];
    __shared__ float meansh;
    if ((i & 31) == 0) sh[i >> 5] = r;
    __syncthreads();
    if (i < 32) {
        float v = sh[i];
        #pragma unroll
        for (int off = 16; off; off >>= 1) v += __shfl_xor_sync(0xffffffffu, v, off);
        if (i == 0) meansh = v * (1.0f/1024.0f);
    }
    __syncthreads();
    float nx = gx / (meansh + 1e-6f);
    float alpha = grn_g[i] * nx + 1.0f;
    g_alpha[b * INTER + i] = alpha;
    int bad = (alpha != 1.0f) || (grn_b[i] != 0.0f);
    int any = __syncthreads_or(bad);
    if (i == 0) g_needfix[b] = any;
}

// ---------------- fixup: only if GRN non-trivial — rewrite A2 in place ----------------
__global__ void fixup_kernel(const float* __restrict__ grn_b) {
    int row = blockIdx.x;             // b*512 + p
    int b = row >> 9;
    if (!g_needfix[b]) return;
    const float* al = g_alpha + b * INTER;
    __half* oh = g_a2 + (size_t)row * INTER;
    int i = threadIdx.x * 2;          // 512 threads x 2
    __half2 hh = *(__half2*)&oh[i];
    float v0 = al[i]     * __half2float(hh.x) + grn_b[i];
    float v1 = al[i + 1] * __half2float(hh.y) + grn_b[i + 1];
    *(__half2*)&oh[i] = __half2(__float2half_rn(v0), __float2half_rn(v1));
}

// ---------------- weight transpose + fp16 ----------------
__global__ void prep_w(const float* __restrict__ pw1_w, const float* __restrict__ pw2_w) {
    int which = blockIdx.z & 1;
    int l = blockIdx.z >> 1;
    const float* src; __half* dh;
    int R, C;
    if (which == 0) { src = pw1_w + (size_t)l * DIM * INTER; R = DIM;  C = INTER;
                      dh = g_w1 + (size_t)l * INTER * DIM; }
    else            { src = pw2_w + (size_t)l * INTER * DIM; R = INTER; C = DIM;
                      dh = g_w2 + (size_t)l * DIM * INTER; }
    int cx = blockIdx.x * 32, ry = blockIdx.y * 32;
    if (cx >= C || ry >= R) return;
    __shared__ float tl[32][33];
    int tx = threadIdx.x, ty = threadIdx.y;
    #pragma unroll
    for (int i = 0; i < 4; i++)
        tl[ty * 4 + i][tx] = src[(size_t)(ry + ty * 4 + i) * C + cx + tx];
    __syncthreads();
    #pragma unroll
    for (int i = 0; i < 4; i++)
        dh[(size_t)(cx + ty * 4 + i) * R + ry + tx] = __float2half_rn(tl[tx][ty * 4 + i]);
}

// ---------------- upsample ----------------
__global__ void upsample_kernel(const int* __restrict__ seq_len, float* __restrict__ out) {
    int bp = blockIdx.x;
    int b = bp >> 12, p = bp & 4095;
    int al = seq_len[b];
    float4* orow = (float4*)(out + (size_t)bp * DIM);
    if (p >= al) {
        for (int c = threadIdx.x; c < DIM / 4; c += blockDim.x)
            orow[c] = make_float4(0.f, 0.f, 0.f, 0.f);
        return;
    }
    int base  = al >> 9;
    int rem   = al & 511;
    int split = (512 - rem) * base;
    int j = (p < split) ? (p / base) : ((512 - rem) + (p - split) / (base + 1));
    if (j > 511) j = 511;
    const float4* xrow = (const float4*)(g_x + (size_t)(b * SEQ + j) * DIM);
    for (int c = threadIdx.x; c < DIM / 4; c += blockDim.x) orow[c] = xrow[c];
}

// ---------------- launch ----------------
extern "C" void kernel_launch(void* const* d_in, const int* in_sizes, int n_in,
                              void* d_out, int out_size) {
    const int*   text    = (const int*)  d_in[0];
    const int*   seq_len = (const int*)  d_in[1];
    const float* emb     = (const float*)d_in[2];
    const float* dw_w    = (const float*)d_in[3];
    const float* dw_b    = (const float*)d_in[4];
    const float* ln_g    = (const float*)d_in[5];
    const float* ln_b    = (const float*)d_in[6];
    const float* pw1_w   = (const float*)d_in[7];
    const float* pw1_b   = (const float*)d_in[8];
    const float* grn_g   = (const float*)d_in[9];
    const float* grn_b   = (const float*)d_in[10];
    const float* pw2_w   = (const float*)d_in[11];
    const float* pw2_b   = (const float*)d_in[12];
    float* out = (float*)d_out;

    static const int SMEM_BYTES = NSTAGE * (int)STAGE_BYTES;  // 96 KB
    cudaFuncSetAttribute(gemm1_mma, cudaFuncAttributeMaxDynamicSharedMemorySize, SMEM_BYTES);
    cudaFuncSetAttribute(gemm2_mma, cudaFuncAttributeMaxDynamicSharedMemorySize, SMEM_BYTES);

    prep_w<<<dim3(32, 32, 2 * NLAYERS), dim3(32, 8)>>>(pw1_w, pw2_w);
    embed_kernel<<<NB * SEQ, 256>>>(text, emb);
    for (int l = 0; l < NLAYERS; l++) {
        convln_kernel<<<NB * P1, 128>>>(dw_w + l * 7 * DIM, dw_b + l * DIM,
                                        ln_g + l * DIM, ln_b + l * DIM);
        gemm1_mma<<<dim3(INTER / 128, M1T), 128, SMEM_BYTES>>>(l, pw1_b + l * INTER);
        alpha_kernel<<<NB, 1024>>>(grn_g + l * INTER, grn_b + l * INTER);
        fixup_kernel<<<NB * SEQ, 512>>>(grn_b + l * INTER);
        gemm2_mma<<<dim3(DIM / 128, NB * SEQ / 128, 2), 128, SMEM_BYTES>>>(l, pw2_b + l * DIM);
    }
    upsample_kernel<<<NB * MAXSEQ, 128>>>(seq_len, out);
}